// round 5
// baseline (speedup 1.0000x reference)
#include <cuda_runtime.h>
#include <math.h>

// ---------------- problem constants ----------------
constexpr int B_   = 4;
constexpr int T_   = 2048;
constexpr int DM   = 1024;   // d_model
constexpr int DI   = 2048;   // d_inner
constexpr int DS   = 16;     // d_state
constexpr int DTR  = 32;     // dt_rank
constexpr int M_   = B_ * T_;      // 8192 rows
constexpr int NXZ  = 2 * DI;       // 4096 (xz width)

// ---------------- scratch (device globals; no cudaMalloc allowed) -------------
__device__ float g_xz[(size_t)M_ * NXZ];   // 134 MB : [m, 4096]  (x_in | z)
__device__ float g_u [(size_t)M_ * DI];    // 67 MB  : conv+silu output
__device__ float g_dt[(size_t)M_ * DI];    // 67 MB  : softplus dt
__device__ float g_ys[(size_t)M_ * DI];    // 67 MB  : y * silu(z)
__device__ float g_dmean;

// ---------------- helpers ----------------
__device__ __forceinline__ float silu_f(float x) {
    return x / (1.0f + __expf(-x));
}
__device__ __forceinline__ float softplus_f(float x) {
    return (x > 20.0f) ? x : log1pf(__expf(x));
}

// ---------------- Dv mean ----------------
__global__ void dmean_kernel(const float* __restrict__ Dv) {
    __shared__ float s[256];
    float v = 0.f;
    for (int i = threadIdx.x; i < DI; i += 256) v += Dv[i];
    s[threadIdx.x] = v;
    __syncthreads();
    for (int o = 128; o > 0; o >>= 1) {
        if (threadIdx.x < o) s[threadIdx.x] += s[threadIdx.x + o];
        __syncthreads();
    }
    if (threadIdx.x == 0) g_dmean = s[0] / (float)DI;
}

// ---------------- SGEMM: C[M,N] = A[M,K] @ Bw[N,K]^T + bias[N] (+ resid*dmean) --
#define BM 128
#define BN 128
#define BKK 8
#define TM 8
#define TN 8

__global__ __launch_bounds__(256)
void sgemm_tn(const float* __restrict__ A, const float* __restrict__ Bw,
              const float* __restrict__ bias, float* __restrict__ C,
              int M, int N, int K,
              const float* __restrict__ resid)   // may be null
{
    __shared__ float As[BKK][BM];
    __shared__ float Bs[BKK][BN];

    const int tid  = threadIdx.x;
    const int row0 = blockIdx.y * BM;
    const int col0 = blockIdx.x * BN;

    const int l_row = tid >> 1;          // 0..127
    const int l_col = (tid & 1) * 4;     // 0 or 4

    const int tx = tid & 15;             // 0..15 -> N direction
    const int ty = tid >> 4;             // 0..15 -> M direction

    float acc[TM][TN];
#pragma unroll
    for (int i = 0; i < TM; i++)
#pragma unroll
        for (int j = 0; j < TN; j++) acc[i][j] = 0.f;

    const float* Aptr = A + (size_t)(row0 + l_row) * K + l_col;
    const float* Bptr = Bw + (size_t)(col0 + l_row) * K + l_col;

    for (int k0 = 0; k0 < K; k0 += BKK) {
        float4 av = *(const float4*)(Aptr + k0);
        float4 bv = *(const float4*)(Bptr + k0);
        As[l_col + 0][l_row] = av.x;
        As[l_col + 1][l_row] = av.y;
        As[l_col + 2][l_row] = av.z;
        As[l_col + 3][l_row] = av.w;
        Bs[l_col + 0][l_row] = bv.x;
        Bs[l_col + 1][l_row] = bv.y;
        Bs[l_col + 2][l_row] = bv.z;
        Bs[l_col + 3][l_row] = bv.w;
        __syncthreads();

#pragma unroll
        for (int k = 0; k < BKK; k++) {
            float4 ra0 = *(const float4*)&As[k][ty * TM];
            float4 ra1 = *(const float4*)&As[k][ty * TM + 4];
            float4 rb0 = *(const float4*)&Bs[k][tx * TN];
            float4 rb1 = *(const float4*)&Bs[k][tx * TN + 4];
            float ra[TM] = {ra0.x, ra0.y, ra0.z, ra0.w, ra1.x, ra1.y, ra1.z, ra1.w};
            float rb[TN] = {rb0.x, rb0.y, rb0.z, rb0.w, rb1.x, rb1.y, rb1.z, rb1.w};
#pragma unroll
            for (int i = 0; i < TM; i++)
#pragma unroll
                for (int j = 0; j < TN; j++)
                    acc[i][j] = fmaf(ra[i], rb[j], acc[i][j]);
        }
        __syncthreads();
    }

    const float dm = (resid != nullptr) ? g_dmean : 0.f;
#pragma unroll
    for (int i = 0; i < TM; i++) {
        const int r = row0 + ty * TM + i;
#pragma unroll
        for (int j = 0; j < TN; j++) {
            const int c = col0 + tx * TN + j;
            float v = acc[i][j] + bias[c];
            if (resid != nullptr) v += resid[(size_t)r * N + c] * dm;
            C[(size_t)r * N + c] = v;
        }
    }
}

// ---------------- fused depthwise conv + SiLU + dt projection + softplus -------
// grid: (DI/256, T_/TT, B_), block 256. Each thread: one channel d, TT timesteps.
#define TT 16
__global__ __launch_bounds__(256)
void conv_dt_kernel(const float* __restrict__ conv_w, const float* __restrict__ conv_b,
                    const float* __restrict__ Wdt, const float* __restrict__ bdt)
{
    __shared__ float sx[TT][DTR];   // x_in[t0..t0+15, 0:32]

    const int tid = threadIdx.x;
    const int d   = blockIdx.x * 256 + tid;
    const int t0  = blockIdx.y * TT;
    const int b   = blockIdx.z;

    // load x_in[:, 0:32] slab for these timesteps
    for (int i = tid; i < TT * DTR; i += 256) {
        int tt = i / DTR, rr = i % DTR;
        sx[tt][rr] = g_xz[(size_t)(b * T_ + t0 + tt) * NXZ + rr];
    }
    __syncthreads();

    // per-channel parameters
    const float w0 = conv_w[d * 4 + 0];
    const float w1 = conv_w[d * 4 + 1];
    const float w2 = conv_w[d * 4 + 2];
    const float w3 = conv_w[d * 4 + 3];
    const float cb = conv_b[d];
    const float bd = bdt[d];
    float wdt[DTR];
#pragma unroll
    for (int r = 0; r < DTR; r++) wdt[r] = Wdt[d * DTR + r];

    // sliding causal window x[t-3], x[t-2], x[t-1]
    float x3 = (t0 >= 3) ? g_xz[(size_t)(b * T_ + t0 - 3) * NXZ + d] : 0.f;
    float x2 = (t0 >= 2) ? g_xz[(size_t)(b * T_ + t0 - 2) * NXZ + d] : 0.f;
    float x1 = (t0 >= 1) ? g_xz[(size_t)(b * T_ + t0 - 1) * NXZ + d] : 0.f;

#pragma unroll
    for (int tt = 0; tt < TT; tt++) {
        const int t = t0 + tt;
        const size_t m = (size_t)(b * T_ + t);

        float xc = g_xz[m * NXZ + d];

        // dt = softplus(x_in[:, :32] @ Wdt[d,:] + bdt[d])
        float dtr = bd;
#pragma unroll
        for (int r = 0; r < DTR; r++) dtr = fmaf(sx[tt][r], wdt[r], dtr);
        float dt = softplus_f(dtr);

        // depthwise causal conv-4 + bias + silu
        float a = cb;
        a = fmaf(w0, x3, a);
        a = fmaf(w1, x2, a);
        a = fmaf(w2, x1, a);
        a = fmaf(w3, xc, a);
        float u = silu_f(a);

        x3 = x2; x2 = x1; x1 = xc;

        g_dt[m * DI + d] = dt;
        g_u [m * DI + d] = u;
    }
}

// ---------------- selective scan --------------------------------------------
// One warp handles 2 channels (16 lanes = 16 states each). Block = 8 warps = 16 ch.
// grid: (DI/16, B_). Writes ys = y * silu(z).
__global__ __launch_bounds__(256)
void scan_kernel(const float* __restrict__ A_log, const float* __restrict__ Bm,
                 const float* __restrict__ Cm)
{
    const int tid  = threadIdx.x;
    const int warp = tid >> 5;
    const int lane = tid & 31;
    const int d    = blockIdx.x * 16 + warp * 2 + (lane >> 4);
    const int n    = lane & 15;
    const int b    = blockIdx.y;

    const float a   = -__expf(A_log[d * DS + n]);
    const float al2 = a * 1.44269504088896f;       // for exp2f
    const float bm  = Bm[d * DS + n];
    const float cm  = Cm[d * DS + n];

    const float* pdt = g_dt + (size_t)b * T_ * DI + d;
    const float* pu  = g_u  + (size_t)b * T_ * DI + d;
    const float* pz  = g_xz + (size_t)b * T_ * NXZ + DI + d;
    float*       pys = g_ys + (size_t)b * T_ * DI + d;

    float h = 0.f;
#pragma unroll 4
    for (int t = 0; t < T_; t++) {
        const float dtv = pdt[(size_t)t * DI];
        const float uv  = pu [(size_t)t * DI];
        const float e   = exp2f(dtv * al2);
        h = fmaf(h, e, dtv * bm * uv);
        float p = h * cm;
        // sum over 16 states (butterfly within 16-lane halves)
        p += __shfl_xor_sync(0xffffffffu, p, 1);
        p += __shfl_xor_sync(0xffffffffu, p, 2);
        p += __shfl_xor_sync(0xffffffffu, p, 4);
        p += __shfl_xor_sync(0xffffffffu, p, 8);
        if (n == 0) {
            const float zv = pz[(size_t)t * NXZ];
            pys[(size_t)t * DI] = p * silu_f(zv);
        }
    }
}

// ---------------- launch ------------------------------------------------------
extern "C" void kernel_launch(void* const* d_in, const int* in_sizes, int n_in,
                              void* d_out, int out_size)
{
    const float* x      = (const float*)d_in[0];
    const float* Wi     = (const float*)d_in[1];
    const float* bi     = (const float*)d_in[2];
    const float* conv_w = (const float*)d_in[3];
    const float* conv_b = (const float*)d_in[4];
    const float* Wdt    = (const float*)d_in[5];
    const float* bdt    = (const float*)d_in[6];
    const float* A_log  = (const float*)d_in[7];
    const float* Bm     = (const float*)d_in[8];
    const float* Cm     = (const float*)d_in[9];
    const float* Dv     = (const float*)d_in[10];
    const float* Wo     = (const float*)d_in[11];
    const float* bo     = (const float*)d_in[12];
    float* out = (float*)d_out;

    float* xz_p; cudaGetSymbolAddress((void**)&xz_p, g_xz);
    float* ys_p; cudaGetSymbolAddress((void**)&ys_p, g_ys);

    // 0) Dv mean
    dmean_kernel<<<1, 256>>>(Dv);

    // 1) xz = x @ Wi^T + bi     (M=8192, N=4096, K=1024)
    {
        dim3 grid(NXZ / BN, M_ / BM);
        sgemm_tn<<<grid, 256>>>(x, Wi, bi, xz_p, M_, NXZ, DM, nullptr);
    }

    // 2) conv + silu -> u ; dt projection + softplus -> dt
    {
        dim3 grid(DI / 256, T_ / TT, B_);
        conv_dt_kernel<<<grid, 256>>>(conv_w, conv_b, Wdt, bdt);
    }

    // 3) selective scan -> ys = y * silu(z)
    {
        dim3 grid(DI / 16, B_);
        scan_kernel<<<grid, 256>>>(A_log, Bm, Cm);
    }

    // 4) out = ys @ Wo^T + bo + x * mean(Dv)   (M=8192, N=1024, K=2048)
    {
        dim3 grid(DM / BN, M_ / BM);
        sgemm_tn<<<grid, 256>>>(ys_p, Wo, bo, out, M_, DM, DI, x);
    }
}

// round 7
// speedup vs baseline: 1.4878x; 1.4878x over previous
#include <cuda_runtime.h>
#include <math.h>

// ---------------- problem constants ----------------
constexpr int B_   = 4;
constexpr int T_   = 2048;
constexpr int DM   = 1024;   // d_model
constexpr int DI   = 2048;   // d_inner
constexpr int DS   = 16;     // d_state
constexpr int DTR  = 32;     // dt_rank
constexpr int M_   = B_ * T_;      // 8192 rows
constexpr int NXZ  = 2 * DI;       // 4096 (xz width)

// ---------------- scratch (device globals; no cudaMalloc allowed) -------------
__device__ float g_xz[(size_t)M_ * NXZ];   // 134 MB : [m, 4096]  (x_in | z)
__device__ float g_u [(size_t)M_ * DI];    // 67 MB  : conv+silu output
__device__ float g_dt[(size_t)M_ * DI];    // 67 MB  : softplus dt
__device__ float g_ys[(size_t)M_ * DI];    // 67 MB  : y * silu(z)
__device__ float g_dmean;

// ---------------- helpers ----------------
__device__ __forceinline__ float silu_f(float x) {
    return x / (1.0f + __expf(-x));
}
__device__ __forceinline__ float softplus_f(float x) {
    return (x > 20.0f) ? x : log1pf(__expf(x));
}
__device__ __forceinline__ unsigned tf32_rn(float f) {
    unsigned r;
    asm("cvt.rna.tf32.f32 %0, %1;" : "=r"(r) : "f"(f));
    return r;
}

// ---------------- Dv mean ----------------
__global__ void dmean_kernel(const float* __restrict__ Dv) {
    __shared__ float s[256];
    float v = 0.f;
    for (int i = threadIdx.x; i < DI; i += 256) v += Dv[i];
    s[threadIdx.x] = v;
    __syncthreads();
    for (int o = 128; o > 0; o >>= 1) {
        if (threadIdx.x < o) s[threadIdx.x] += s[threadIdx.x + o];
        __syncthreads();
    }
    if (threadIdx.x == 0) g_dmean = s[0] / (float)DI;
}

// =====================================================================
// TF32 tensor-core GEMM:  C[M,N] = A[M,K] @ Bw[N,K]^T + bias[N] (+resid*dmean)
// Block tile 128x128, BK=16, double-buffered smem, 8 warps (4M x 2N),
// warp tile 32x64 = 2x8 m16n8k8 mma tiles.
// =====================================================================
#define GBM 128
#define GBN 128
#define GBK 16
#define AS_STRIDE (GBK + 4)   // 20: conflict-free for A-frag reads
#define BS_STRIDE (GBN + 4)   // 132: conflict-free for B-frag reads

__device__ __forceinline__ void mma_tf32(float& d0, float& d1, float& d2, float& d3,
                                         unsigned a0, unsigned a1, unsigned a2, unsigned a3,
                                         unsigned b0, unsigned b1)
{
    asm volatile(
        "mma.sync.aligned.m16n8k8.row.col.f32.tf32.tf32.f32 "
        "{%0,%1,%2,%3}, {%4,%5,%6,%7}, {%8,%9}, {%0,%1,%2,%3};"
        : "+f"(d0), "+f"(d1), "+f"(d2), "+f"(d3)
        : "r"(a0), "r"(a1), "r"(a2), "r"(a3), "r"(b0), "r"(b1));
}

__global__ __launch_bounds__(256)
void gemm_tf32(const float* __restrict__ A, const float* __restrict__ Bw,
               const float* __restrict__ bias, float* __restrict__ C,
               int M, int N, int K,
               const float* __restrict__ resid)   // may be null
{
    __shared__ unsigned As[2][GBM][AS_STRIDE];   // [m][k], tf32 bits
    __shared__ unsigned Bs[2][GBK][BS_STRIDE];   // [k][n], tf32 bits

    const int tid  = threadIdx.x;
    const int warp = tid >> 5;
    const int lane = tid & 31;
    const int wm   = warp & 3;    // 0..3  -> 32-row slab
    const int wn   = warp >> 2;   // 0..1  -> 64-col slab

    const int row0 = blockIdx.y * GBM;
    const int col0 = blockIdx.x * GBN;

    // global load mapping: 2 float4 per thread per tile per chunk
    const int lrowA0 = (tid + 0)   >> 2, lcolA0 = ((tid + 0)   & 3) * 4;
    const int lrowA1 = (tid + 256) >> 2, lcolA1 = ((tid + 256) & 3) * 4;

    float acc[2][8][4];
#pragma unroll
    for (int mt = 0; mt < 2; mt++)
#pragma unroll
        for (int nt = 0; nt < 8; nt++)
#pragma unroll
            for (int j = 0; j < 4; j++) acc[mt][nt][j] = 0.f;

    const int NK = K / GBK;

    // ---- preload chunk 0 ----
    {
        float4 a0 = *(const float4*)(A  + (size_t)(row0 + lrowA0) * K + lcolA0);
        float4 a1 = *(const float4*)(A  + (size_t)(row0 + lrowA1) * K + lcolA1);
        float4 b0 = *(const float4*)(Bw + (size_t)(col0 + lrowA0) * K + lcolA0);
        float4 b1 = *(const float4*)(Bw + (size_t)(col0 + lrowA1) * K + lcolA1);
        As[0][lrowA0][lcolA0+0] = tf32_rn(a0.x); As[0][lrowA0][lcolA0+1] = tf32_rn(a0.y);
        As[0][lrowA0][lcolA0+2] = tf32_rn(a0.z); As[0][lrowA0][lcolA0+3] = tf32_rn(a0.w);
        As[0][lrowA1][lcolA1+0] = tf32_rn(a1.x); As[0][lrowA1][lcolA1+1] = tf32_rn(a1.y);
        As[0][lrowA1][lcolA1+2] = tf32_rn(a1.z); As[0][lrowA1][lcolA1+3] = tf32_rn(a1.w);
        // B tile: rows are N-dim (col0+lrow), cols are K. Store transposed into Bs[k][n].
        Bs[0][lcolA0+0][lrowA0] = tf32_rn(b0.x); Bs[0][lcolA0+1][lrowA0] = tf32_rn(b0.y);
        Bs[0][lcolA0+2][lrowA0] = tf32_rn(b0.z); Bs[0][lcolA0+3][lrowA0] = tf32_rn(b0.w);
        Bs[0][lcolA1+0][lrowA1] = tf32_rn(b1.x); Bs[0][lcolA1+1][lrowA1] = tf32_rn(b1.y);
        Bs[0][lcolA1+2][lrowA1] = tf32_rn(b1.z); Bs[0][lcolA1+3][lrowA1] = tf32_rn(b1.w);
    }
    __syncthreads();

    const int mrow = wm * 32 + (lane >> 2);     // within-block m for a-frags
    const int ncol = wn * 64 + (lane >> 2);     // within-block n base for b-frags
    const int kq   = lane & 3;                  // k quad index

    for (int k0 = 0; k0 < NK; k0++) {
        const int buf = k0 & 1;

        // prefetch next chunk into registers
        float4 pa0, pa1, pb0, pb1;
        if (k0 + 1 < NK) {
            const int kb = (k0 + 1) * GBK;
            pa0 = *(const float4*)(A  + (size_t)(row0 + lrowA0) * K + kb + lcolA0);
            pa1 = *(const float4*)(A  + (size_t)(row0 + lrowA1) * K + kb + lcolA1);
            pb0 = *(const float4*)(Bw + (size_t)(col0 + lrowA0) * K + kb + lcolA0);
            pb1 = *(const float4*)(Bw + (size_t)(col0 + lrowA1) * K + kb + lcolA1);
        }

        // compute on current buffer: 2 k-steps of 8
#pragma unroll
        for (int ks = 0; ks < 2; ks++) {
            const int kk = ks * 8;
            unsigned af[2][4];
#pragma unroll
            for (int mt = 0; mt < 2; mt++) {
                const int r = mrow + mt * 16;
                af[mt][0] = As[buf][r    ][kk + kq];
                af[mt][1] = As[buf][r + 8][kk + kq];
                af[mt][2] = As[buf][r    ][kk + 4 + kq];
                af[mt][3] = As[buf][r + 8][kk + 4 + kq];
            }
            unsigned bf[8][2];
#pragma unroll
            for (int nt = 0; nt < 8; nt++) {
                const int c = ncol + nt * 8;
                bf[nt][0] = Bs[buf][kk + kq    ][c];
                bf[nt][1] = Bs[buf][kk + 4 + kq][c];
            }
#pragma unroll
            for (int mt = 0; mt < 2; mt++)
#pragma unroll
                for (int nt = 0; nt < 8; nt++)
                    mma_tf32(acc[mt][nt][0], acc[mt][nt][1], acc[mt][nt][2], acc[mt][nt][3],
                             af[mt][0], af[mt][1], af[mt][2], af[mt][3],
                             bf[nt][0], bf[nt][1]);
        }

        // stage next chunk into other buffer
        if (k0 + 1 < NK) {
            const int nb = buf ^ 1;
            As[nb][lrowA0][lcolA0+0] = tf32_rn(pa0.x); As[nb][lrowA0][lcolA0+1] = tf32_rn(pa0.y);
            As[nb][lrowA0][lcolA0+2] = tf32_rn(pa0.z); As[nb][lrowA0][lcolA0+3] = tf32_rn(pa0.w);
            As[nb][lrowA1][lcolA1+0] = tf32_rn(pa1.x); As[nb][lrowA1][lcolA1+1] = tf32_rn(pa1.y);
            As[nb][lrowA1][lcolA1+2] = tf32_rn(pa1.z); As[nb][lrowA1][lcolA1+3] = tf32_rn(pa1.w);
            Bs[nb][lcolA0+0][lrowA0] = tf32_rn(pb0.x); Bs[nb][lcolA0+1][lrowA0] = tf32_rn(pb0.y);
            Bs[nb][lcolA0+2][lrowA0] = tf32_rn(pb0.z); Bs[nb][lcolA0+3][lrowA0] = tf32_rn(pb0.w);
            Bs[nb][lcolA1+0][lrowA1] = tf32_rn(pb1.x); Bs[nb][lcolA1+1][lrowA1] = tf32_rn(pb1.y);
            Bs[nb][lcolA1+2][lrowA1] = tf32_rn(pb1.z); Bs[nb][lcolA1+3][lrowA1] = tf32_rn(pb1.w);
        }
        __syncthreads();
    }

    // ---- epilogue: bias + optional residual, float2 stores ----
    const float dm = (resid != nullptr) ? g_dmean : 0.f;
#pragma unroll
    for (int mt = 0; mt < 2; mt++) {
        const int r0 = row0 + wm * 32 + mt * 16 + (lane >> 2);
        const int r1 = r0 + 8;
#pragma unroll
        for (int nt = 0; nt < 8; nt++) {
            const int c = col0 + wn * 64 + nt * 8 + (lane & 3) * 2;
            const float b0v = bias[c], b1v = bias[c + 1];
            float v00 = acc[mt][nt][0] + b0v;
            float v01 = acc[mt][nt][1] + b1v;
            float v10 = acc[mt][nt][2] + b0v;
            float v11 = acc[mt][nt][3] + b1v;
            if (resid != nullptr) {
                v00 += resid[(size_t)r0 * N + c    ] * dm;
                v01 += resid[(size_t)r0 * N + c + 1] * dm;
                v10 += resid[(size_t)r1 * N + c    ] * dm;
                v11 += resid[(size_t)r1 * N + c + 1] * dm;
            }
            *(float2*)(C + (size_t)r0 * N + c) = make_float2(v00, v01);
            *(float2*)(C + (size_t)r1 * N + c) = make_float2(v10, v11);
        }
    }
}

// ---------------- fused depthwise conv + SiLU + dt projection + softplus -------
#define TT 16
__global__ __launch_bounds__(256)
void conv_dt_kernel(const float* __restrict__ conv_w, const float* __restrict__ conv_b,
                    const float* __restrict__ Wdt, const float* __restrict__ bdt)
{
    __shared__ float sx[TT][DTR];   // x_in[t0..t0+15, 0:32]

    const int tid = threadIdx.x;
    const int d   = blockIdx.x * 256 + tid;
    const int t0  = blockIdx.y * TT;
    const int b   = blockIdx.z;

    for (int i = tid; i < TT * DTR; i += 256) {
        int tt = i / DTR, rr = i % DTR;
        sx[tt][rr] = g_xz[(size_t)(b * T_ + t0 + tt) * NXZ + rr];
    }
    __syncthreads();

    const float w0 = conv_w[d * 4 + 0];
    const float w1 = conv_w[d * 4 + 1];
    const float w2 = conv_w[d * 4 + 2];
    const float w3 = conv_w[d * 4 + 3];
    const float cb = conv_b[d];
    const float bd = bdt[d];
    float wdt[DTR];
#pragma unroll
    for (int r = 0; r < DTR; r++) wdt[r] = Wdt[d * DTR + r];

    float x3 = (t0 >= 3) ? g_xz[(size_t)(b * T_ + t0 - 3) * NXZ + d] : 0.f;
    float x2 = (t0 >= 2) ? g_xz[(size_t)(b * T_ + t0 - 2) * NXZ + d] : 0.f;
    float x1 = (t0 >= 1) ? g_xz[(size_t)(b * T_ + t0 - 1) * NXZ + d] : 0.f;

#pragma unroll
    for (int tt = 0; tt < TT; tt++) {
        const int t = t0 + tt;
        const size_t m = (size_t)(b * T_ + t);

        float xc = g_xz[m * NXZ + d];

        float dtr = bd;
#pragma unroll
        for (int r = 0; r < DTR; r++) dtr = fmaf(sx[tt][r], wdt[r], dtr);
        float dt = softplus_f(dtr);

        float a = cb;
        a = fmaf(w0, x3, a);
        a = fmaf(w1, x2, a);
        a = fmaf(w2, x1, a);
        a = fmaf(w3, xc, a);
        float u = silu_f(a);

        x3 = x2; x2 = x1; x1 = xc;

        g_dt[m * DI + d] = dt;
        g_u [m * DI + d] = u;
    }
}

// ---------------- selective scan --------------------------------------------
__global__ __launch_bounds__(256)
void scan_kernel(const float* __restrict__ A_log, const float* __restrict__ Bm,
                 const float* __restrict__ Cm)
{
    const int tid  = threadIdx.x;
    const int warp = tid >> 5;
    const int lane = tid & 31;
    const int d    = blockIdx.x * 16 + warp * 2 + (lane >> 4);
    const int n    = lane & 15;
    const int b    = blockIdx.y;

    const float a   = -__expf(A_log[d * DS + n]);
    const float al2 = a * 1.44269504088896f;
    const float bm  = Bm[d * DS + n];
    const float cm  = Cm[d * DS + n];

    const float* pdt = g_dt + (size_t)b * T_ * DI + d;
    const float* pu  = g_u  + (size_t)b * T_ * DI + d;
    const float* pz  = g_xz + (size_t)b * T_ * NXZ + DI + d;
    float*       pys = g_ys + (size_t)b * T_ * DI + d;

    float h = 0.f;
#pragma unroll 4
    for (int t = 0; t < T_; t++) {
        const float dtv = pdt[(size_t)t * DI];
        const float uv  = pu [(size_t)t * DI];
        const float e   = exp2f(dtv * al2);
        h = fmaf(h, e, dtv * bm * uv);
        float p = h * cm;
        p += __shfl_xor_sync(0xffffffffu, p, 1);
        p += __shfl_xor_sync(0xffffffffu, p, 2);
        p += __shfl_xor_sync(0xffffffffu, p, 4);
        p += __shfl_xor_sync(0xffffffffu, p, 8);
        if (n == 0) {
            const float zv = pz[(size_t)t * NXZ];
            pys[(size_t)t * DI] = p * silu_f(zv);
        }
    }
}

// ---------------- launch ------------------------------------------------------
extern "C" void kernel_launch(void* const* d_in, const int* in_sizes, int n_in,
                              void* d_out, int out_size)
{
    const float* x      = (const float*)d_in[0];
    const float* Wi     = (const float*)d_in[1];
    const float* bi     = (const float*)d_in[2];
    const float* conv_w = (const float*)d_in[3];
    const float* conv_b = (const float*)d_in[4];
    const float* Wdt    = (const float*)d_in[5];
    const float* bdt    = (const float*)d_in[6];
    const float* A_log  = (const float*)d_in[7];
    const float* Bm     = (const float*)d_in[8];
    const float* Cm     = (const float*)d_in[9];
    const float* Dv     = (const float*)d_in[10];
    const float* Wo     = (const float*)d_in[11];
    const float* bo     = (const float*)d_in[12];
    float* out = (float*)d_out;

    float* xz_p; cudaGetSymbolAddress((void**)&xz_p, g_xz);
    float* ys_p; cudaGetSymbolAddress((void**)&ys_p, g_ys);

    // 0) Dv mean
    dmean_kernel<<<1, 256>>>(Dv);

    // 1) xz = x @ Wi^T + bi     (M=8192, N=4096, K=1024)  [tensor core tf32]
    {
        dim3 grid(NXZ / GBN, M_ / GBM);
        gemm_tf32<<<grid, 256>>>(x, Wi, bi, xz_p, M_, NXZ, DM, nullptr);
    }

    // 2) conv + silu -> u ; dt projection + softplus -> dt
    {
        dim3 grid(DI / 256, T_ / TT, B_);
        conv_dt_kernel<<<grid, 256>>>(conv_w, conv_b, Wdt, bdt);
    }

    // 3) selective scan -> ys = y * silu(z)
    {
        dim3 grid(DI / 16, B_);
        scan_kernel<<<grid, 256>>>(A_log, Bm, Cm);
    }

    // 4) out = ys @ Wo^T + bo + x * mean(Dv)   (M=8192, N=1024, K=2048)  [tf32]
    {
        dim3 grid(DM / GBN, M_ / GBM);
        gemm_tf32<<<grid, 256>>>(ys_p, Wo, bo, out, M_, DM, DI, x);
    }
}

// round 9
// speedup vs baseline: 1.7864x; 1.2008x over previous
#include <cuda_runtime.h>
#include <cuda_bf16.h>
#include <math.h>
#include <stdint.h>

// ---------------- problem constants ----------------
constexpr int B_   = 4;
constexpr int T_   = 2048;
constexpr int DM   = 1024;   // d_model
constexpr int DI   = 2048;   // d_inner
constexpr int DS   = 16;     // d_state
constexpr int DTR  = 32;     // dt_rank
constexpr int M_   = B_ * T_;      // 8192 rows
constexpr int NXZ  = 2 * DI;       // 4096 (xz width)

// ---------------- scratch (device globals; no cudaMalloc allowed) -------------
__device__ float g_xz[(size_t)M_ * NXZ];            // 134 MB : [m, 4096]  (x_in | z)
__device__ float g_u [(size_t)M_ * DI];             // 67 MB
__device__ float g_dt[(size_t)M_ * DI];             // 67 MB
__device__ __nv_bfloat16 g_xb [(size_t)M_ * DM];    // 16 MB  : x in bf16
__device__ __nv_bfloat16 g_wib[(size_t)NXZ * DM];   // 8 MB   : Wi in bf16
__device__ __nv_bfloat16 g_wob[(size_t)DM * DI];    // 4 MB   : Wo in bf16
__device__ __nv_bfloat16 g_ysb[(size_t)M_ * DI];    // 32 MB  : ys in bf16
__device__ float g_dmean;

// ---------------- helpers ----------------
__device__ __forceinline__ float silu_f(float x) { return x / (1.0f + __expf(-x)); }
__device__ __forceinline__ float softplus_f(float x) {
    return (x > 20.0f) ? x : log1pf(__expf(x));
}
__device__ __forceinline__ uint32_t smem_u32(const void* p) {
    uint32_t a;
    asm("{ .reg .u64 t; cvta.to.shared.u64 t, %1; cvt.u32.u64 %0, t; }" : "=r"(a) : "l"(p));
    return a;
}
__device__ __forceinline__ void cp16(uint32_t dst, const void* src) {
    asm volatile("cp.async.cg.shared.global [%0], [%1], 16;" :: "r"(dst), "l"(src) : "memory");
}
#define CP_COMMIT() asm volatile("cp.async.commit_group;" ::: "memory")
#define CP_WAIT(n)  asm volatile("cp.async.wait_group %0;" :: "n"(n) : "memory")

#define LDSM4(r, addr)                                                          \
    asm volatile("ldmatrix.sync.aligned.m8n8.x4.shared.b16 {%0,%1,%2,%3}, [%4];"\
        : "=r"((r)[0]), "=r"((r)[1]), "=r"((r)[2]), "=r"((r)[3]) : "r"(addr))

__device__ __forceinline__ void mma_bf16(float* d, const uint32_t* a,
                                         uint32_t b0, uint32_t b1) {
    asm volatile(
        "mma.sync.aligned.m16n8k16.row.col.f32.bf16.bf16.f32 "
        "{%0,%1,%2,%3}, {%4,%5,%6,%7}, {%8,%9}, {%0,%1,%2,%3};"
        : "+f"(d[0]), "+f"(d[1]), "+f"(d[2]), "+f"(d[3])
        : "r"(a[0]), "r"(a[1]), "r"(a[2]), "r"(a[3]), "r"(b0), "r"(b1));
}

// ---------------- Dv mean ----------------
__global__ void dmean_kernel(const float* __restrict__ Dv) {
    __shared__ float s[256];
    float v = 0.f;
    for (int i = threadIdx.x; i < DI; i += 256) v += Dv[i];
    s[threadIdx.x] = v;
    __syncthreads();
    for (int o = 128; o > 0; o >>= 1) {
        if (threadIdx.x < o) s[threadIdx.x] += s[threadIdx.x + o];
        __syncthreads();
    }
    if (threadIdx.x == 0) g_dmean = s[0] / (float)DI;
}

// ---------------- fp32 -> bf16 convert (8 elems/thread) ----------------
__global__ void f32_to_bf16_kernel(const float* __restrict__ src,
                                   __nv_bfloat16* __restrict__ dst, int n8) {
    int i = blockIdx.x * blockDim.x + threadIdx.x;
    if (i >= n8) return;
    size_t idx = (size_t)i * 8;
    float4 a = *(const float4*)(src + idx);
    float4 b = *(const float4*)(src + idx + 4);
    __nv_bfloat162 p0 = __float22bfloat162_rn(make_float2(a.x, a.y));
    __nv_bfloat162 p1 = __float22bfloat162_rn(make_float2(a.z, a.w));
    __nv_bfloat162 p2 = __float22bfloat162_rn(make_float2(b.x, b.y));
    __nv_bfloat162 p3 = __float22bfloat162_rn(make_float2(b.z, b.w));
    uint4 o;
    o.x = *(uint32_t*)&p0; o.y = *(uint32_t*)&p1;
    o.z = *(uint32_t*)&p2; o.w = *(uint32_t*)&p3;
    *(uint4*)(dst + idx) = o;
}

// =====================================================================
// bf16 mma.sync GEMM:  C[M,N] = A[M,K] @ Bw[N,K]^T + bias[N] (+resid*dmean)
// 128x128 block, BK=32, 4-stage cp.async, ldmatrix fragments.
// 8 warps: 2 (M) x 4 (N); warp tile 64x32 = 4x4 m16n8k16 tiles.
// Smem rows pitched to 80 B (5 x 16B chunks; 5 coprime 8 -> conflict-free).
// =====================================================================
constexpr int BM = 128, BN = 128, BK = 32, STAGES = 4;
constexpr int PITCH   = 80;                 // bytes per 32-bf16 row (64 + 16 pad)
constexpr int A_STAGE = BM * PITCH;         // 10240
constexpr int B_STAGE = BN * PITCH;         // 10240
constexpr int STG     = A_STAGE + B_STAGE;  // 20480
constexpr int GSMEM   = STAGES * STG;       // 81920

__global__ __launch_bounds__(256)
void gemm_bf16(const __nv_bfloat16* __restrict__ A, const __nv_bfloat16* __restrict__ Bw,
               const float* __restrict__ bias, float* __restrict__ C,
               int K, int N, const float* __restrict__ resid)
{
    extern __shared__ __align__(128) char smem[];
    const uint32_t sb = smem_u32(smem);

    const int tid  = threadIdx.x;
    const int warp = tid >> 5;
    const int lane = tid & 31;
    const int row0 = blockIdx.y * BM;
    const int col0 = blockIdx.x * BN;
    const int warp_m = (warp >> 2) * 64;
    const int warp_n = (warp & 3) * 32;
    const int NK = K / BK;

    // cp.async chunk mapping: thread handles chunk ids tid and tid+256.
    // id -> (row = id>>2, c = id&3); 16B per chunk; gmem row-major K-contig.
    const int r0 = tid >> 2,         c0 = tid & 3;
    const int r1 = (tid + 256) >> 2, c1 = (tid + 256) & 3;

    // ldmatrix per-lane offsets (within stage)
    const int mlane = lane & 15, kselA = lane >> 4;
    uint32_t aoff[4];
#pragma unroll
    for (int mt = 0; mt < 4; mt++)
        aoff[mt] = (uint32_t)(warp_m + mt * 16 + mlane) * PITCH + kselA * 16;
    const int nlane = (lane & 7) + ((lane & 16) >> 1);
    const int kselB = (lane >> 3) & 1;
    uint32_t boff[2];
#pragma unroll
    for (int nt2 = 0; nt2 < 2; nt2++)
        boff[nt2] = A_STAGE + (uint32_t)(warp_n + nt2 * 16 + nlane) * PITCH + kselB * 16;

    float acc[4][4][4];
#pragma unroll
    for (int mt = 0; mt < 4; mt++)
#pragma unroll
        for (int nt = 0; nt < 4; nt++)
#pragma unroll
            for (int j = 0; j < 4; j++) acc[mt][nt][j] = 0.f;

    // stage loader
    auto load_stage = [&](int cidx) {
        const uint32_t base = sb + (cidx & (STAGES - 1)) * STG;
        const int kofs = cidx * BK;
        cp16(base + (uint32_t)r0 * PITCH + c0 * 16,
             A + (size_t)(row0 + r0) * K + kofs + c0 * 8);
        cp16(base + (uint32_t)r1 * PITCH + c1 * 16,
             A + (size_t)(row0 + r1) * K + kofs + c1 * 8);
        cp16(base + A_STAGE + (uint32_t)r0 * PITCH + c0 * 16,
             Bw + (size_t)(col0 + r0) * K + kofs + c0 * 8);
        cp16(base + A_STAGE + (uint32_t)r1 * PITCH + c1 * 16,
             Bw + (size_t)(col0 + r1) * K + kofs + c1 * 8);
        CP_COMMIT();
    };

#pragma unroll
    for (int s = 0; s < STAGES - 1; s++) load_stage(s);

    for (int c = 0; c < NK; c++) {
        CP_WAIT(STAGES - 2);
        __syncthreads();
        if (c + STAGES - 1 < NK) load_stage(c + STAGES - 1);

        const uint32_t stage = sb + (c & (STAGES - 1)) * STG;
#pragma unroll
        for (int ks = 0; ks < 2; ks++) {
            uint32_t af[4][4], bf[2][4];
#pragma unroll
            for (int mt = 0; mt < 4; mt++) LDSM4(af[mt], stage + aoff[mt] + ks * 32);
#pragma unroll
            for (int nt2 = 0; nt2 < 2; nt2++) LDSM4(bf[nt2], stage + boff[nt2] + ks * 32);
#pragma unroll
            for (int mt = 0; mt < 4; mt++)
#pragma unroll
                for (int nt = 0; nt < 4; nt++)
                    mma_bf16(acc[mt][nt], af[mt],
                             bf[nt >> 1][(nt & 1) * 2 + 0],
                             bf[nt >> 1][(nt & 1) * 2 + 1]);
        }
    }

    // ---- epilogue: bias + optional residual ----
    const float dm = (resid != nullptr) ? g_dmean : 0.f;
    const int trow = lane >> 2;
    const int tcol = (lane & 3) * 2;
#pragma unroll
    for (int mt = 0; mt < 4; mt++) {
        const int rA = row0 + warp_m + mt * 16 + trow;
        const int rB = rA + 8;
#pragma unroll
        for (int nt = 0; nt < 4; nt++) {
            const int cc = col0 + warp_n + nt * 8 + tcol;
            const float b0v = bias[cc], b1v = bias[cc + 1];
            float v00 = acc[mt][nt][0] + b0v;
            float v01 = acc[mt][nt][1] + b1v;
            float v10 = acc[mt][nt][2] + b0v;
            float v11 = acc[mt][nt][3] + b1v;
            if (resid != nullptr) {
                v00 += resid[(size_t)rA * N + cc    ] * dm;
                v01 += resid[(size_t)rA * N + cc + 1] * dm;
                v10 += resid[(size_t)rB * N + cc    ] * dm;
                v11 += resid[(size_t)rB * N + cc + 1] * dm;
            }
            *(float2*)(C + (size_t)rA * N + cc) = make_float2(v00, v01);
            *(float2*)(C + (size_t)rB * N + cc) = make_float2(v10, v11);
        }
    }
}

// ---------------- fused depthwise conv + SiLU + dt projection + softplus -------
#define TT 16
__global__ __launch_bounds__(256)
void conv_dt_kernel(const float* __restrict__ conv_w, const float* __restrict__ conv_b,
                    const float* __restrict__ Wdt, const float* __restrict__ bdt)
{
    __shared__ float sx[TT][DTR];

    const int tid = threadIdx.x;
    const int d   = blockIdx.x * 256 + tid;
    const int t0  = blockIdx.y * TT;
    const int b   = blockIdx.z;

    for (int i = tid; i < TT * DTR; i += 256) {
        int tt = i / DTR, rr = i % DTR;
        sx[tt][rr] = g_xz[(size_t)(b * T_ + t0 + tt) * NXZ + rr];
    }
    __syncthreads();

    const float w0 = conv_w[d * 4 + 0];
    const float w1 = conv_w[d * 4 + 1];
    const float w2 = conv_w[d * 4 + 2];
    const float w3 = conv_w[d * 4 + 3];
    const float cb = conv_b[d];
    const float bd = bdt[d];
    float wdt[DTR];
#pragma unroll
    for (int r = 0; r < DTR; r++) wdt[r] = Wdt[d * DTR + r];

    float x3 = (t0 >= 3) ? g_xz[(size_t)(b * T_ + t0 - 3) * NXZ + d] : 0.f;
    float x2 = (t0 >= 2) ? g_xz[(size_t)(b * T_ + t0 - 2) * NXZ + d] : 0.f;
    float x1 = (t0 >= 1) ? g_xz[(size_t)(b * T_ + t0 - 1) * NXZ + d] : 0.f;

#pragma unroll
    for (int tt = 0; tt < TT; tt++) {
        const int t = t0 + tt;
        const size_t m = (size_t)(b * T_ + t);

        float xc = g_xz[m * NXZ + d];

        float dtr = bd;
#pragma unroll
        for (int r = 0; r < DTR; r++) dtr = fmaf(sx[tt][r], wdt[r], dtr);
        float dt = softplus_f(dtr);

        float a = cb;
        a = fmaf(w0, x3, a);
        a = fmaf(w1, x2, a);
        a = fmaf(w2, x1, a);
        a = fmaf(w3, xc, a);
        float u = silu_f(a);

        x3 = x2; x2 = x1; x1 = xc;

        g_dt[m * DI + d] = dt;
        g_u [m * DI + d] = u;
    }
}

// ---------------- selective scan (writes ys directly as bf16) ----------------
__global__ __launch_bounds__(256)
void scan_kernel(const float* __restrict__ A_log, const float* __restrict__ Bm,
                 const float* __restrict__ Cm)
{
    const int tid  = threadIdx.x;
    const int warp = tid >> 5;
    const int lane = tid & 31;
    const int d    = blockIdx.x * 16 + warp * 2 + (lane >> 4);
    const int n    = lane & 15;
    const int b    = blockIdx.y;

    const float a   = -__expf(A_log[d * DS + n]);
    const float al2 = a * 1.44269504088896f;
    const float bm  = Bm[d * DS + n];
    const float cm  = Cm[d * DS + n];

    const float* pdt = g_dt + (size_t)b * T_ * DI + d;
    const float* pu  = g_u  + (size_t)b * T_ * DI + d;
    const float* pz  = g_xz + (size_t)b * T_ * NXZ + DI + d;
    __nv_bfloat16* pys = g_ysb + (size_t)b * T_ * DI + d;

    float h = 0.f;
#pragma unroll 4
    for (int t = 0; t < T_; t++) {
        const float dtv = pdt[(size_t)t * DI];
        const float uv  = pu [(size_t)t * DI];
        const float e   = exp2f(dtv * al2);
        h = fmaf(h, e, dtv * bm * uv);
        float p = h * cm;
        p += __shfl_xor_sync(0xffffffffu, p, 1);
        p += __shfl_xor_sync(0xffffffffu, p, 2);
        p += __shfl_xor_sync(0xffffffffu, p, 4);
        p += __shfl_xor_sync(0xffffffffu, p, 8);
        if (n == 0) {
            const float zv = pz[(size_t)t * NXZ];
            pys[(size_t)t * DI] = __float2bfloat16_rn(p * silu_f(zv));
        }
    }
}

// ---------------- launch ------------------------------------------------------
extern "C" void kernel_launch(void* const* d_in, const int* in_sizes, int n_in,
                              void* d_out, int out_size)
{
    const float* x      = (const float*)d_in[0];
    const float* Wi     = (const float*)d_in[1];
    const float* bi     = (const float*)d_in[2];
    const float* conv_w = (const float*)d_in[3];
    const float* conv_b = (const float*)d_in[4];
    const float* Wdt    = (const float*)d_in[5];
    const float* bdt    = (const float*)d_in[6];
    const float* A_log  = (const float*)d_in[7];
    const float* Bm     = (const float*)d_in[8];
    const float* Cm     = (const float*)d_in[9];
    const float* Dv     = (const float*)d_in[10];
    const float* Wo     = (const float*)d_in[11];
    const float* bo     = (const float*)d_in[12];
    float* out = (float*)d_out;

    float* xz_p;  cudaGetSymbolAddress((void**)&xz_p,  g_xz);
    __nv_bfloat16* xb_p;  cudaGetSymbolAddress((void**)&xb_p,  g_xb);
    __nv_bfloat16* wib_p; cudaGetSymbolAddress((void**)&wib_p, g_wib);
    __nv_bfloat16* wob_p; cudaGetSymbolAddress((void**)&wob_p, g_wob);
    __nv_bfloat16* ysb_p; cudaGetSymbolAddress((void**)&ysb_p, g_ysb);

    cudaFuncSetAttribute(gemm_bf16, cudaFuncAttributeMaxDynamicSharedMemorySize, GSMEM);

    // 0) Dv mean + bf16 conversions
    dmean_kernel<<<1, 256>>>(Dv);
    f32_to_bf16_kernel<<<(M_ * DM / 8 + 255) / 256, 256>>>(x, xb_p, M_ * DM / 8);
    f32_to_bf16_kernel<<<(NXZ * DM / 8 + 255) / 256, 256>>>(Wi, wib_p, NXZ * DM / 8);
    f32_to_bf16_kernel<<<(DM * DI / 8 + 255) / 256, 256>>>(Wo, wob_p, DM * DI / 8);

    // 1) xz = x @ Wi^T + bi   (M=8192, N=4096, K=1024)  [bf16 mma.sync]
    {
        dim3 grid(NXZ / BN, M_ / BM);   // (32, 64)
        gemm_bf16<<<grid, 256, GSMEM>>>(xb_p, wib_p, bi, xz_p, DM, NXZ, nullptr);
    }

    // 2) conv + silu -> u ; dt projection + softplus -> dt
    {
        dim3 grid(DI / 256, T_ / TT, B_);
        conv_dt_kernel<<<grid, 256>>>(conv_w, conv_b, Wdt, bdt);
    }

    // 3) selective scan -> ysb = bf16(y * silu(z))
    {
        dim3 grid(DI / 16, B_);
        scan_kernel<<<grid, 256>>>(A_log, Bm, Cm);
    }

    // 4) out = ys @ Wo^T + bo + x * mean(Dv)  (M=8192, N=1024, K=2048) [bf16]
    {
        dim3 grid(DM / BN, M_ / BM);    // (8, 64)
        gemm_bf16<<<grid, 256, GSMEM>>>(ysb_p, wob_p, bo, out, DI, DM, x);
    }
}

// round 10
// speedup vs baseline: 1.8342x; 1.0268x over previous
#include <cuda_runtime.h>
#include <cuda_bf16.h>
#include <math.h>
#include <stdint.h>

// ---------------- problem constants ----------------
constexpr int B_   = 4;
constexpr int T_   = 2048;
constexpr int DM   = 1024;   // d_model
constexpr int DI   = 2048;   // d_inner
constexpr int DS   = 16;     // d_state
constexpr int DTR  = 32;     // dt_rank
constexpr int M_   = B_ * T_;      // 8192 rows
constexpr int NXZ  = 2 * DI;       // 4096 (xz width)

// ---------------- scratch (device globals; no cudaMalloc allowed) -------------
__device__ float g_xz[(size_t)M_ * NXZ];            // 134 MB : [m, 4096]  (x_in | z)
__device__ float g_u [(size_t)M_ * DI];             // 67 MB
__device__ float g_dt[(size_t)M_ * DI];             // 67 MB
__device__ __nv_bfloat16 g_xb [(size_t)M_ * DM];    // 16 MB  : x in bf16
__device__ __nv_bfloat16 g_wib[(size_t)NXZ * DM];   // 8 MB   : Wi in bf16
__device__ __nv_bfloat16 g_wob[(size_t)DM * DI];    // 4 MB   : Wo in bf16
__device__ __nv_bfloat16 g_ysb[(size_t)M_ * DI];    // 32 MB  : ys in bf16
__device__ float g_dmean;

// ---------------- helpers ----------------
__device__ __forceinline__ float silu_f(float x) { return x / (1.0f + __expf(-x)); }
__device__ __forceinline__ float softplus_f(float x) {
    return (x > 20.0f) ? x : log1pf(__expf(x));
}
__device__ __forceinline__ uint32_t smem_u32(const void* p) {
    uint32_t a;
    asm("{ .reg .u64 t; cvta.to.shared.u64 t, %1; cvt.u32.u64 %0, t; }" : "=r"(a) : "l"(p));
    return a;
}
__device__ __forceinline__ void cp16(uint32_t dst, const void* src) {
    asm volatile("cp.async.cg.shared.global [%0], [%1], 16;" :: "r"(dst), "l"(src) : "memory");
}
#define CP_COMMIT() asm volatile("cp.async.commit_group;" ::: "memory")
#define CP_WAIT(n)  asm volatile("cp.async.wait_group %0;" :: "n"(n) : "memory")

#define LDSM4(r, addr)                                                          \
    asm volatile("ldmatrix.sync.aligned.m8n8.x4.shared.b16 {%0,%1,%2,%3}, [%4];"\
        : "=r"((r)[0]), "=r"((r)[1]), "=r"((r)[2]), "=r"((r)[3]) : "r"(addr))

__device__ __forceinline__ void mma_bf16(float* d, const uint32_t* a,
                                         uint32_t b0, uint32_t b1) {
    asm volatile(
        "mma.sync.aligned.m16n8k16.row.col.f32.bf16.bf16.f32 "
        "{%0,%1,%2,%3}, {%4,%5,%6,%7}, {%8,%9}, {%0,%1,%2,%3};"
        : "+f"(d[0]), "+f"(d[1]), "+f"(d[2]), "+f"(d[3])
        : "r"(a[0]), "r"(a[1]), "r"(a[2]), "r"(a[3]), "r"(b0), "r"(b1));
}

// ---------------- Dv mean ----------------
__global__ void dmean_kernel(const float* __restrict__ Dv) {
    __shared__ float s[256];
    float v = 0.f;
    for (int i = threadIdx.x; i < DI; i += 256) v += Dv[i];
    s[threadIdx.x] = v;
    __syncthreads();
    for (int o = 128; o > 0; o >>= 1) {
        if (threadIdx.x < o) s[threadIdx.x] += s[threadIdx.x + o];
        __syncthreads();
    }
    if (threadIdx.x == 0) g_dmean = s[0] / (float)DI;
}

// ---------------- fp32 -> bf16 convert (8 elems/thread) ----------------
__global__ void f32_to_bf16_kernel(const float* __restrict__ src,
                                   __nv_bfloat16* __restrict__ dst, int n8) {
    int i = blockIdx.x * blockDim.x + threadIdx.x;
    if (i >= n8) return;
    size_t idx = (size_t)i * 8;
    float4 a = *(const float4*)(src + idx);
    float4 b = *(const float4*)(src + idx + 4);
    __nv_bfloat162 p0 = __float22bfloat162_rn(make_float2(a.x, a.y));
    __nv_bfloat162 p1 = __float22bfloat162_rn(make_float2(a.z, a.w));
    __nv_bfloat162 p2 = __float22bfloat162_rn(make_float2(b.x, b.y));
    __nv_bfloat162 p3 = __float22bfloat162_rn(make_float2(b.z, b.w));
    uint4 o;
    o.x = *(uint32_t*)&p0; o.y = *(uint32_t*)&p1;
    o.z = *(uint32_t*)&p2; o.w = *(uint32_t*)&p3;
    *(uint4*)(dst + idx) = o;
}

// =====================================================================
// bf16 mma.sync GEMM:  C[M,N] = A[M,K] @ Bw[N,K]^T + bias[N] (+resid*dmean)
// 128x128 block, BK=32, 3-stage cp.async, ldmatrix fragments.
// 8 warps: 2 (M) x 4 (N); warp tile 64x32 = 4x4 m16n8k16 tiles.
// Smem rows pitched to 80 B (5 x 16B chunks; 5 coprime 8 -> conflict-free).
// 60 KB dynamic smem => 2 CTAs/SM (latency hiding across co-resident CTAs).
// =====================================================================
constexpr int BM = 128, BN = 128, BK = 32, STAGES = 3;
constexpr int PITCH   = 80;                 // bytes per 32-bf16 row (64 + 16 pad)
constexpr int A_STAGE = BM * PITCH;         // 10240
constexpr int B_STAGE = BN * PITCH;         // 10240
constexpr int STG     = A_STAGE + B_STAGE;  // 20480
constexpr int GSMEM   = STAGES * STG;       // 61440

__global__ __launch_bounds__(256, 2)
void gemm_bf16(const __nv_bfloat16* __restrict__ A, const __nv_bfloat16* __restrict__ Bw,
               const float* __restrict__ bias, float* __restrict__ C,
               int K, int N, const float* __restrict__ resid)
{
    extern __shared__ __align__(128) char smem[];
    const uint32_t sb = smem_u32(smem);

    const int tid  = threadIdx.x;
    const int warp = tid >> 5;
    const int lane = tid & 31;
    const int row0 = blockIdx.y * BM;
    const int col0 = blockIdx.x * BN;
    const int warp_m = (warp >> 2) * 64;
    const int warp_n = (warp & 3) * 32;
    const int NK = K / BK;

    // cp.async chunk mapping: thread handles chunk ids tid and tid+256.
    const int r0 = tid >> 2,         c0 = tid & 3;
    const int r1 = (tid + 256) >> 2, c1 = (tid + 256) & 3;

    // ldmatrix per-lane offsets (within stage)
    const int mlane = lane & 15, kselA = lane >> 4;
    uint32_t aoff[4];
#pragma unroll
    for (int mt = 0; mt < 4; mt++)
        aoff[mt] = (uint32_t)(warp_m + mt * 16 + mlane) * PITCH + kselA * 16;
    const int nlane = (lane & 7) + ((lane & 16) >> 1);
    const int kselB = (lane >> 3) & 1;
    uint32_t boff[2];
#pragma unroll
    for (int nt2 = 0; nt2 < 2; nt2++)
        boff[nt2] = A_STAGE + (uint32_t)(warp_n + nt2 * 16 + nlane) * PITCH + kselB * 16;

    float acc[4][4][4];
#pragma unroll
    for (int mt = 0; mt < 4; mt++)
#pragma unroll
        for (int nt = 0; nt < 4; nt++)
#pragma unroll
            for (int j = 0; j < 4; j++) acc[mt][nt][j] = 0.f;

    // stage index rotation without modulo
    auto stage_of = [&](int cidx) -> uint32_t {
        int s = cidx % STAGES;
        return sb + (uint32_t)s * STG;
    };

    auto load_stage = [&](int cidx) {
        const uint32_t base = stage_of(cidx);
        const int kofs = cidx * BK;
        cp16(base + (uint32_t)r0 * PITCH + c0 * 16,
             A + (size_t)(row0 + r0) * K + kofs + c0 * 8);
        cp16(base + (uint32_t)r1 * PITCH + c1 * 16,
             A + (size_t)(row0 + r1) * K + kofs + c1 * 8);
        cp16(base + A_STAGE + (uint32_t)r0 * PITCH + c0 * 16,
             Bw + (size_t)(col0 + r0) * K + kofs + c0 * 8);
        cp16(base + A_STAGE + (uint32_t)r1 * PITCH + c1 * 16,
             Bw + (size_t)(col0 + r1) * K + kofs + c1 * 8);
        CP_COMMIT();
    };

#pragma unroll
    for (int s = 0; s < STAGES - 1; s++) load_stage(s);

    for (int c = 0; c < NK; c++) {
        CP_WAIT(STAGES - 2);
        __syncthreads();
        if (c + STAGES - 1 < NK) load_stage(c + STAGES - 1);

        const uint32_t stage = stage_of(c);
#pragma unroll
        for (int ks = 0; ks < 2; ks++) {
            uint32_t af[4][4], bf[2][4];
#pragma unroll
            for (int mt = 0; mt < 4; mt++) LDSM4(af[mt], stage + aoff[mt] + ks * 32);
#pragma unroll
            for (int nt2 = 0; nt2 < 2; nt2++) LDSM4(bf[nt2], stage + boff[nt2] + ks * 32);
#pragma unroll
            for (int mt = 0; mt < 4; mt++)
#pragma unroll
                for (int nt = 0; nt < 4; nt++)
                    mma_bf16(acc[mt][nt], af[mt],
                             bf[nt >> 1][(nt & 1) * 2 + 0],
                             bf[nt >> 1][(nt & 1) * 2 + 1]);
        }
    }

    // ---- epilogue: bias + optional residual ----
    const float dm = (resid != nullptr) ? g_dmean : 0.f;
    const int trow = lane >> 2;
    const int tcol = (lane & 3) * 2;
#pragma unroll
    for (int mt = 0; mt < 4; mt++) {
        const int rA = row0 + warp_m + mt * 16 + trow;
        const int rB = rA + 8;
#pragma unroll
        for (int nt = 0; nt < 4; nt++) {
            const int cc = col0 + warp_n + nt * 8 + tcol;
            const float b0v = bias[cc], b1v = bias[cc + 1];
            float v00 = acc[mt][nt][0] + b0v;
            float v01 = acc[mt][nt][1] + b1v;
            float v10 = acc[mt][nt][2] + b0v;
            float v11 = acc[mt][nt][3] + b1v;
            if (resid != nullptr) {
                v00 += resid[(size_t)rA * N + cc    ] * dm;
                v01 += resid[(size_t)rA * N + cc + 1] * dm;
                v10 += resid[(size_t)rB * N + cc    ] * dm;
                v11 += resid[(size_t)rB * N + cc + 1] * dm;
            }
            *(float2*)(C + (size_t)rA * N + cc) = make_float2(v00, v01);
            *(float2*)(C + (size_t)rB * N + cc) = make_float2(v10, v11);
        }
    }
}

// ---------------- fused depthwise conv + SiLU + dt projection + softplus -------
#define TT 16
__global__ __launch_bounds__(256)
void conv_dt_kernel(const float* __restrict__ conv_w, const float* __restrict__ conv_b,
                    const float* __restrict__ Wdt, const float* __restrict__ bdt)
{
    __shared__ float sx[TT][DTR];

    const int tid = threadIdx.x;
    const int d   = blockIdx.x * 256 + tid;
    const int t0  = blockIdx.y * TT;
    const int b   = blockIdx.z;

    for (int i = tid; i < TT * DTR; i += 256) {
        int tt = i / DTR, rr = i % DTR;
        sx[tt][rr] = g_xz[(size_t)(b * T_ + t0 + tt) * NXZ + rr];
    }
    __syncthreads();

    const float w0 = conv_w[d * 4 + 0];
    const float w1 = conv_w[d * 4 + 1];
    const float w2 = conv_w[d * 4 + 2];
    const float w3 = conv_w[d * 4 + 3];
    const float cb = conv_b[d];
    const float bd = bdt[d];
    float wdt[DTR];
#pragma unroll
    for (int r = 0; r < DTR; r++) wdt[r] = Wdt[d * DTR + r];

    float x3 = (t0 >= 3) ? g_xz[(size_t)(b * T_ + t0 - 3) * NXZ + d] : 0.f;
    float x2 = (t0 >= 2) ? g_xz[(size_t)(b * T_ + t0 - 2) * NXZ + d] : 0.f;
    float x1 = (t0 >= 1) ? g_xz[(size_t)(b * T_ + t0 - 1) * NXZ + d] : 0.f;

#pragma unroll
    for (int tt = 0; tt < TT; tt++) {
        const int t = t0 + tt;
        const size_t m = (size_t)(b * T_ + t);

        float xc = g_xz[m * NXZ + d];

        float dtr = bd;
#pragma unroll
        for (int r = 0; r < DTR; r++) dtr = fmaf(sx[tt][r], wdt[r], dtr);
        float dt = softplus_f(dtr);

        float a = cb;
        a = fmaf(w0, x3, a);
        a = fmaf(w1, x2, a);
        a = fmaf(w2, x1, a);
        a = fmaf(w3, xc, a);
        float u = silu_f(a);

        x3 = x2; x2 = x1; x1 = xc;

        g_dt[m * DI + d] = dt;
        g_u [m * DI + d] = u;
    }
}

// ---------------- selective scan (writes ys directly as bf16) ----------------
__global__ __launch_bounds__(256)
void scan_kernel(const float* __restrict__ A_log, const float* __restrict__ Bm,
                 const float* __restrict__ Cm)
{
    const int tid  = threadIdx.x;
    const int warp = tid >> 5;
    const int lane = tid & 31;
    const int d    = blockIdx.x * 16 + warp * 2 + (lane >> 4);
    const int n    = lane & 15;
    const int b    = blockIdx.y;

    const float a   = -__expf(A_log[d * DS + n]);
    const float al2 = a * 1.44269504088896f;
    const float bm  = Bm[d * DS + n];
    const float cm  = Cm[d * DS + n];

    const float* pdt = g_dt + (size_t)b * T_ * DI + d;
    const float* pu  = g_u  + (size_t)b * T_ * DI + d;
    const float* pz  = g_xz + (size_t)b * T_ * NXZ + DI + d;
    __nv_bfloat16* pys = g_ysb + (size_t)b * T_ * DI + d;

    float h = 0.f;
#pragma unroll 4
    for (int t = 0; t < T_; t++) {
        const float dtv = pdt[(size_t)t * DI];
        const float uv  = pu [(size_t)t * DI];
        const float e   = exp2f(dtv * al2);
        h = fmaf(h, e, dtv * bm * uv);
        float p = h * cm;
        p += __shfl_xor_sync(0xffffffffu, p, 1);
        p += __shfl_xor_sync(0xffffffffu, p, 2);
        p += __shfl_xor_sync(0xffffffffu, p, 4);
        p += __shfl_xor_sync(0xffffffffu, p, 8);
        if (n == 0) {
            const float zv = pz[(size_t)t * NXZ];
            pys[(size_t)t * DI] = __float2bfloat16_rn(p * silu_f(zv));
        }
    }
}

// ---------------- launch ------------------------------------------------------
extern "C" void kernel_launch(void* const* d_in, const int* in_sizes, int n_in,
                              void* d_out, int out_size)
{
    const float* x      = (const float*)d_in[0];
    const float* Wi     = (const float*)d_in[1];
    const float* bi     = (const float*)d_in[2];
    const float* conv_w = (const float*)d_in[3];
    const float* conv_b = (const float*)d_in[4];
    const float* Wdt    = (const float*)d_in[5];
    const float* bdt    = (const float*)d_in[6];
    const float* A_log  = (const float*)d_in[7];
    const float* Bm     = (const float*)d_in[8];
    const float* Cm     = (const float*)d_in[9];
    const float* Dv     = (const float*)d_in[10];
    const float* Wo     = (const float*)d_in[11];
    const float* bo     = (const float*)d_in[12];
    float* out = (float*)d_out;

    float* xz_p;  cudaGetSymbolAddress((void**)&xz_p,  g_xz);
    __nv_bfloat16* xb_p;  cudaGetSymbolAddress((void**)&xb_p,  g_xb);
    __nv_bfloat16* wib_p; cudaGetSymbolAddress((void**)&wib_p, g_wib);
    __nv_bfloat16* wob_p; cudaGetSymbolAddress((void**)&wob_p, g_wob);
    __nv_bfloat16* ysb_p; cudaGetSymbolAddress((void**)&ysb_p, g_ysb);

    cudaFuncSetAttribute(gemm_bf16, cudaFuncAttributeMaxDynamicSharedMemorySize, GSMEM);

    // 0) Dv mean + bf16 conversions
    dmean_kernel<<<1, 256>>>(Dv);
    f32_to_bf16_kernel<<<(M_ * DM / 8 + 255) / 256, 256>>>(x, xb_p, M_ * DM / 8);
    f32_to_bf16_kernel<<<(NXZ * DM / 8 + 255) / 256, 256>>>(Wi, wib_p, NXZ * DM / 8);
    f32_to_bf16_kernel<<<(DM * DI / 8 + 255) / 256, 256>>>(Wo, wob_p, DM * DI / 8);

    // 1) xz = x @ Wi^T + bi   (M=8192, N=4096, K=1024)  [bf16 mma.sync]
    {
        dim3 grid(NXZ / BN, M_ / BM);   // (32, 64)
        gemm_bf16<<<grid, 256, GSMEM>>>(xb_p, wib_p, bi, xz_p, DM, NXZ, nullptr);
    }

    // 2) conv + silu -> u ; dt projection + softplus -> dt
    {
        dim3 grid(DI / 256, T_ / TT, B_);
        conv_dt_kernel<<<grid, 256>>>(conv_w, conv_b, Wdt, bdt);
    }

    // 3) selective scan -> ysb = bf16(y * silu(z))
    {
        dim3 grid(DI / 16, B_);
        scan_kernel<<<grid, 256>>>(A_log, Bm, Cm);
    }

    // 4) out = ys @ Wo^T + bo + x * mean(Dv)  (M=8192, N=1024, K=2048) [bf16]
    {
        dim3 grid(DM / BN, M_ / BM);    // (8, 64)
        gemm_bf16<<<grid, 256, GSMEM>>>(ysb_p, wob_p, bo, out, DI, DM, x);
    }
}